// round 2
// baseline (speedup 1.0000x reference)
#include <cuda_runtime.h>
#include <math.h>

#define B    16
#define D    2048
#define T    100
#define N0   4096
#define N1   4096
#define N2   2048
#define NCLS 10

__device__ __constant__ float c_zero = 0.0f;

constexpr float DECAY = 0.9f;
constexpr float THRESH = 1.0f;
constexpr float LR = 0.01f;
constexpr float TRD = 0.95f;

// ---------------- device state ----------------
__device__ float g_Wa[(size_t)N0 * N1];          // 64 MB
__device__ float g_Wb[(size_t)N1 * N2];          // 32 MB
__device__ float g_s0f[(size_t)(T + 1) * N0 * B]; // s0 spikes (floats), slot s = step s-1, slot0 = 0
__device__ float g_p0f[(size_t)(T + 1) * N0 * B]; // p0 trace
__device__ float g_s1f[2][N1 * B];               // ping-pong s1 (layout [j][b])
__device__ float g_s2f[N2 * B];                  // s2 prev      (layout [j][b])
__device__ float g_q0n[N1 * B];                  // -q0          (layout [j][b])
__device__ float g_q1n[N2 * B];                  // -q1          (layout [j][b])
__device__ float g_p1[N1 * B];                   // p1           (layout [i][b])
__device__ float g_V1[B * N1];
__device__ float g_V2[B * N2];
__device__ int   g_r1[B * N1];
__device__ int   g_r2[B * N2];
__device__ float g_cur1[B * N1];
__device__ float g_cur2[B * N2];
__device__ float g_cnt[B * N2];
__device__ float g_racc[B * N0];

// ---------------- f32x2 helpers ----------------
typedef unsigned long long u64;
__device__ __forceinline__ u64 pack2(float lo, float hi) {
    u64 r; asm("mov.b64 %0, {%1,%2};" : "=l"(r) : "f"(lo), "f"(hi)); return r;
}
__device__ __forceinline__ void unpack2(u64 v, float& lo, float& hi) {
    asm("mov.b64 {%0,%1}, %2;" : "=f"(lo), "=f"(hi) : "l"(v));
}
__device__ __forceinline__ void fma2(u64& acc, u64 a, u64 b) {
    asm("fma.rn.f32x2 %0, %1, %2, %0;" : "+l"(acc) : "l"(a), "l"(b));
}

// ---------------- init ----------------
__global__ void k_init() {
    int i = blockIdx.x * blockDim.x + threadIdx.x;
    int n = gridDim.x * blockDim.x;
    for (int k = i; k < N0 * B; k += n) { g_s0f[k] = 0.f; g_p0f[k] = 0.f; g_racc[k] = 0.f; }
    for (int k = i; k < N1 * B; k += n) {
        g_s1f[0][k] = 0.f; g_s1f[1][k] = 0.f; g_q0n[k] = 0.f; g_p1[k] = 0.f;
        g_V1[k] = 0.f; g_r1[k] = 0; g_cur1[k] = 0.f;
    }
    for (int k = i; k < N2 * B; k += n) {
        g_s2f[k] = 0.f; g_q1n[k] = 0.f; g_V2[k] = 0.f; g_r2[k] = 0;
        g_cur2[k] = 0.f; g_cnt[k] = 0.f;
    }
}

// ---------------- encoder GEMM: racc[b,i] = sum_d x[b,d] * Wenc[d,i] ----------------
__global__ void k_enc(const float* __restrict__ x, const float* __restrict__ Wenc) {
    __shared__ float xs[B][128];
    int i = blockIdx.x * 128 + threadIdx.x;
    int d0 = blockIdx.y * 128;
    for (int k = threadIdx.x; k < B * 128; k += 128) {
        int b = k / 128, dl = k % 128;
        xs[b][dl] = x[b * D + d0 + dl];
    }
    __syncthreads();
    float acc[B];
#pragma unroll
    for (int b = 0; b < B; b++) acc[b] = 0.f;
    for (int dl = 0; dl < 128; dl++) {
        float w = Wenc[(size_t)(d0 + dl) * N0 + i];
#pragma unroll
        for (int b = 0; b < B; b++) acc[b] = fmaf(xs[b][dl], w, acc[b]);
    }
#pragma unroll
    for (int b = 0; b < B; b++) atomicAdd(&g_racc[b * N0 + i], acc[b]);
}

// ---------------- precompute s0/p0 for all T (layer-0 LIF is recurrence-free) ----------------
__global__ void k_pre(const float* __restrict__ u, const float* __restrict__ benc) {
    int idx = blockIdx.x * blockDim.x + threadIdx.x; // over N0*B, b fast
    int i = idx / B, b = idx % B;
    float rate = 1.f / (1.f + expf(-(g_racc[b * N0 + i] + benc[i])));
    float V = 0.f, p = 0.f;
    int refr = 0;
    const float* up = u + (size_t)b * T * N0 + i;
    for (int t = 0; t < T; t++) {
        float s_in = (up[(size_t)t * N0] < rate) ? 1.f : 0.f;
        V = DECAY * V + s_in;
        bool spk = (V > THRESH) && (refr <= 0);
        float s = spk ? 1.f : 0.f;
        V = spk ? 0.f : V;
        refr = spk ? 2 : (refr > 0 ? refr - 1 : 0);
        p = TRD * p + s;
        size_t o = (size_t)(t + 1) * N0 * B + (size_t)i * B + b;
        g_s0f[o] = s;
        g_p0f[o] = p;
    }
}

// ---------------- Wa pass: fused STDP update (step t-1) + GEMM cur1(t) ----------------
#define TIA 256
__global__ __launch_bounds__(128, 4) void k_wa(int t) {
    __shared__ float sp0[TIA * B];   // p0(t-1)
    __shared__ float ss0p[TIA * B];  // s0(t-1)
    __shared__ float ss0c[TIA * B];  // s0(t)
    int j = blockIdx.x * 128 + threadIdx.x;
    int i0 = blockIdx.y * TIA;
    const float* s1prev = g_s1f[(t & 1) ^ 1];

    u64 s1p[8], q0nn[8], acc[8];
    {
        const float4* sp = (const float4*)(s1prev + (size_t)j * B);
        const float4* qp = (const float4*)(g_q0n + (size_t)j * B);
#pragma unroll
        for (int q = 0; q < 4; q++) {
            float4 v = sp[q];
            s1p[2 * q] = pack2(v.x, v.y); s1p[2 * q + 1] = pack2(v.z, v.w);
            float4 w = qp[q];
            q0nn[2 * q] = pack2(w.x, w.y); q0nn[2 * q + 1] = pack2(w.z, w.w);
        }
#pragma unroll
        for (int g = 0; g < 8; g++) acc[g] = 0ull;
    }
    {
        size_t basep = (size_t)t * N0 * B + (size_t)i0 * B;
        const float4* a0 = (const float4*)(g_p0f + basep);
        const float4* a1 = (const float4*)(g_s0f + basep);
        const float4* a2 = (const float4*)(g_s0f + basep + (size_t)N0 * B);
        float4* d0 = (float4*)sp0;
        float4* d1 = (float4*)ss0p;
        float4* d2 = (float4*)ss0c;
        for (int k = threadIdx.x; k < TIA * B / 4; k += 128) {
            d0[k] = a0[k]; d1[k] = a1[k]; d2[k] = a2[k];
        }
    }
    __syncthreads();

    float* wp = g_Wa + (size_t)i0 * N1 + j;
#pragma unroll 4
    for (int r = 0; r < TIA; r++) {
        float w = wp[(size_t)r * N1];
        const u64* pp = (const u64*)(sp0 + r * B);
        const u64* sp = (const u64*)(ss0p + r * B);
        const u64* sc = (const u64*)(ss0c + r * B);
        u64 d = 0ull;
#pragma unroll
        for (int g = 0; g < 8; g++) fma2(d, pp[g], s1p[g]);   // + p0 * s1_prev
#pragma unroll
        for (int g = 0; g < 8; g++) fma2(d, sp[g], q0nn[g]);  // - s0_prev * q0
        float lo, hi; unpack2(d, lo, hi);
        float nw = fmaf(LR, lo + hi, w);
        nw = fminf(1.f, fmaxf(-1.f, nw));
        wp[(size_t)r * N1] = nw;
        u64 nw2 = pack2(nw, nw);
#pragma unroll
        for (int g = 0; g < 8; g++) fma2(acc[g], sc[g], nw2); // cur1 += s0_cur * Wa_new
    }
#pragma unroll
    for (int g = 0; g < 8; g++) {
        float lo, hi; unpack2(acc[g], lo, hi);
        atomicAdd(&g_cur1[(2 * g) * N1 + j], lo);
        atomicAdd(&g_cur1[(2 * g + 1) * N1 + j], hi);
    }
}

// ---------------- Wb pass: fused STDP update (step t-1) + GEMM cur2(t) ----------------
#define TIB 128
__global__ __launch_bounds__(128, 4) void k_wb(int t) {
    __shared__ float sp1[TIB * B];   // p1(t-1)
    __shared__ float ss1p[TIB * B];  // s1(t-1)
    __shared__ float ss1c[TIB * B];  // s1(t)
    int j = blockIdx.x * 128 + threadIdx.x;
    int i0 = blockIdx.y * TIB;
    const float* s1prev = g_s1f[(t & 1) ^ 1];
    const float* s1cur  = g_s1f[t & 1];

    u64 s2p[8], q1nn[8], acc[8];
    {
        const float4* sp = (const float4*)(g_s2f + (size_t)j * B);
        const float4* qp = (const float4*)(g_q1n + (size_t)j * B);
#pragma unroll
        for (int q = 0; q < 4; q++) {
            float4 v = sp[q];
            s2p[2 * q] = pack2(v.x, v.y); s2p[2 * q + 1] = pack2(v.z, v.w);
            float4 w = qp[q];
            q1nn[2 * q] = pack2(w.x, w.y); q1nn[2 * q + 1] = pack2(w.z, w.w);
        }
#pragma unroll
        for (int g = 0; g < 8; g++) acc[g] = 0ull;
    }
    {
        const float4* a0 = (const float4*)(g_p1 + (size_t)i0 * B);
        const float4* a1 = (const float4*)(s1prev + (size_t)i0 * B);
        const float4* a2 = (const float4*)(s1cur + (size_t)i0 * B);
        float4* d0 = (float4*)sp1;
        float4* d1 = (float4*)ss1p;
        float4* d2 = (float4*)ss1c;
        for (int k = threadIdx.x; k < TIB * B / 4; k += 128) {
            d0[k] = a0[k]; d1[k] = a1[k]; d2[k] = a2[k];
        }
    }
    __syncthreads();

    float* wp = g_Wb + (size_t)i0 * N2 + j;
#pragma unroll 4
    for (int r = 0; r < TIB; r++) {
        float w = wp[(size_t)r * N2];
        const u64* pp = (const u64*)(sp1 + r * B);
        const u64* sp = (const u64*)(ss1p + r * B);
        const u64* sc = (const u64*)(ss1c + r * B);
        u64 d = 0ull;
#pragma unroll
        for (int g = 0; g < 8; g++) fma2(d, pp[g], s2p[g]);   // + p1 * s2_prev
#pragma unroll
        for (int g = 0; g < 8; g++) fma2(d, sp[g], q1nn[g]);  // - s1_prev * q1
        float lo, hi; unpack2(d, lo, hi);
        float nw = fmaf(LR, lo + hi, w);
        nw = fminf(1.f, fmaxf(-1.f, nw));
        wp[(size_t)r * N2] = nw;
        u64 nw2 = pack2(nw, nw);
#pragma unroll
        for (int g = 0; g < 8; g++) fma2(acc[g], sc[g], nw2); // cur2 += s1_cur * Wb_new
    }
#pragma unroll
    for (int g = 0; g < 8; g++) {
        float lo, hi; unpack2(acc[g], lo, hi);
        atomicAdd(&g_cur2[(2 * g) * N2 + j], lo);
        atomicAdd(&g_cur2[(2 * g + 1) * N2 + j], hi);
    }
}

// ---------------- LIF layer 1 + q0 update, writes s1(t) ----------------
__global__ void k_lif1(int t) {
    int idx = blockIdx.x * blockDim.x + threadIdx.x; // over B*N1
    int b = idx / N1, j = idx % N1;
    float cur = g_cur1[idx];
    g_cur1[idx] = 0.f;
    float V = DECAY * g_V1[idx] + cur;
    int refr = g_r1[idx];
    bool spk = (V > THRESH) && (refr <= 0);
    float s = spk ? 1.f : 0.f;
    g_V1[idx] = spk ? 0.f : V;
    g_r1[idx] = spk ? 2 : (refr > 0 ? refr - 1 : 0);
    g_s1f[t & 1][j * B + b] = s;
    float q = g_q0n[j * B + b];
    g_q0n[j * B + b] = TRD * q - s;   // q0n = -q0
}

// ---------------- LIF layer 2 + q1 + p1 updates + spike counts ----------------
__global__ void k_lif2(int t) {
    int idx = blockIdx.x * blockDim.x + threadIdx.x; // over B*N1
    int b = idx / N1, j = idx % N1;
    float s1 = g_s1f[t & 1][j * B + b];
    g_p1[j * B + b] = TRD * g_p1[j * B + b] + s1;    // p1 trace (uses s1(t), after Wb pass read p1(t-1))
    if (j < N2) {
        int id2 = b * N2 + j;
        float cur = g_cur2[id2];
        g_cur2[id2] = 0.f;
        float V = DECAY * g_V2[id2] + cur;
        int refr = g_r2[id2];
        bool spk = (V > THRESH) && (refr <= 0);
        float s = spk ? 1.f : 0.f;
        g_V2[id2] = spk ? 0.f : V;
        g_r2[id2] = spk ? 2 : (refr > 0 ? refr - 1 : 0);
        g_cnt[id2] += s;
        g_s2f[j * B + b] = s;
        float q = g_q1n[j * B + b];
        g_q1n[j * B + b] = TRD * q - s;              // q1n = -q1
    }
}

// ---------------- readout: out = counts @ W_dec + b_dec ----------------
__global__ void k_out(const float* __restrict__ Wdec, const float* __restrict__ bdec,
                      float* __restrict__ out) {
    int tid = threadIdx.x;
    if (tid >= B * NCLS) return;
    int b = tid / NCLS, c = tid % NCLS;
    float acc = bdec[c];
    for (int k = 0; k < N2; k++)
        acc = fmaf(g_cnt[b * N2 + k], Wdec[k * NCLS + c], acc);
    out[b * NCLS + c] = acc;
}

// ---------------- launch ----------------
extern "C" void kernel_launch(void* const* d_in, const int* in_sizes, int n_in,
                              void* d_out, int out_size) {
    (void)in_sizes; (void)n_in; (void)out_size;
    const float* x    = (const float*)d_in[0];
    const float* u    = (const float*)d_in[1];
    const float* Wenc = (const float*)d_in[2];
    const float* benc = (const float*)d_in[3];
    const float* W0   = (const float*)d_in[4];
    const float* W1   = (const float*)d_in[5];
    const float* Wdec = (const float*)d_in[6];
    const float* bdec = (const float*)d_in[7];
    float* out = (float*)d_out;

    cudaMemcpyToSymbolAsync(g_Wa, W0, sizeof(float) * (size_t)N0 * N1, 0,
                            cudaMemcpyDeviceToDevice, 0);
    cudaMemcpyToSymbolAsync(g_Wb, W1, sizeof(float) * (size_t)N1 * N2, 0,
                            cudaMemcpyDeviceToDevice, 0);
    k_init<<<256, 256>>>();
    k_enc<<<dim3(N0 / 128, D / 128), 128>>>(x, Wenc);
    k_pre<<<(N0 * B) / 256, 256>>>(u, benc);
    for (int t = 0; t < T; t++) {
        k_wa<<<dim3(N1 / 128, N0 / TIA), 128>>>(t);
        k_lif1<<<(B * N1) / 256, 256>>>(t);
        k_wb<<<dim3(N2 / 128, N1 / TIB), 128>>>(t);
        k_lif2<<<(B * N1) / 256, 256>>>(t);
    }
    k_out<<<1, 256>>>(Wdec, bdec, out);
}

// round 3
// speedup vs baseline: 1.0111x; 1.0111x over previous
#include <cuda_runtime.h>
#include <math.h>

#define B    16
#define D    2048
#define T    100
#define N0   4096
#define N1   4096
#define N2   2048
#define NCLS 10

constexpr float DECAY = 0.9f;
constexpr float THRESH = 1.0f;
constexpr float LR = 0.01f;
constexpr float TRD = 0.95f;

// ---------------- device state ----------------
__device__ float g_Wa[(size_t)N0 * N1];           // 64 MB
__device__ float g_Wb[(size_t)N1 * N2];           // 32 MB
__device__ float g_s0f[(size_t)(T + 1) * N0 * B]; // s0 spikes, slot s = step s-1, slot0 = zeros
__device__ float g_p0f[(size_t)(T + 1) * N0 * B]; // p0 trace
__device__ float g_s1f[2][N1 * B];                // ping-pong s1, layout [j][b]
__device__ float g_s2f[N2 * B];                   // s2 prev,  layout [j][b]
__device__ float g_q0n[N1 * B];                   // -q0,      layout [j][b]
__device__ float g_q1n[N2 * B];                   // -q1,      layout [j][b]
__device__ float g_p1[N1 * B];                    // p1,       layout [i][b]
__device__ float g_V1[B * N1];
__device__ float g_V2[B * N2];
__device__ int   g_r1[B * N1];
__device__ int   g_r2[B * N2];
__device__ float g_cur1[B * N1];
__device__ float g_cur2[B * N2];
__device__ float g_cnt[B * N2];
__device__ float g_racc[B * N0];

// ---------------- f32x2 helpers ----------------
typedef unsigned long long u64;
union F4U { float4 f4; u64 u[2]; };
__device__ __forceinline__ u64 pack2(float lo, float hi) {
    u64 r; asm("mov.b64 %0, {%1,%2};" : "=l"(r) : "f"(lo), "f"(hi)); return r;
}
__device__ __forceinline__ void unpack2(u64 v, float& lo, float& hi) {
    asm("mov.b64 {%0,%1}, %2;" : "=f"(lo), "=f"(hi) : "l"(v));
}
__device__ __forceinline__ void fma2(u64& acc, u64 a, u64 b) {
    asm("fma.rn.f32x2 %0, %1, %2, %0;" : "+l"(acc) : "l"(a), "l"(b));
}
__device__ __forceinline__ u64 add2(u64 a, u64 b) {
    u64 r; asm("add.rn.f32x2 %0, %1, %2;" : "=l"(r) : "l"(a), "l"(b)); return r;
}

// ---------------- init ----------------
__global__ void k_init() {
    int i = blockIdx.x * blockDim.x + threadIdx.x;
    int n = gridDim.x * blockDim.x;
    for (int k = i; k < N0 * B; k += n) { g_s0f[k] = 0.f; g_p0f[k] = 0.f; g_racc[k] = 0.f; }
    for (int k = i; k < N1 * B; k += n) {
        g_s1f[0][k] = 0.f; g_s1f[1][k] = 0.f; g_q0n[k] = 0.f; g_p1[k] = 0.f;
        g_V1[k] = 0.f; g_r1[k] = 0; g_cur1[k] = 0.f;
    }
    for (int k = i; k < N2 * B; k += n) {
        g_s2f[k] = 0.f; g_q1n[k] = 0.f; g_V2[k] = 0.f; g_r2[k] = 0;
        g_cur2[k] = 0.f; g_cnt[k] = 0.f;
    }
}

// ---------------- encoder GEMM: racc[b,i] = sum_d x[b,d] * Wenc[d,i] ----------------
__global__ void k_enc(const float* __restrict__ x, const float* __restrict__ Wenc) {
    __shared__ float xs[B][128];
    int i = blockIdx.x * 128 + threadIdx.x;
    int d0 = blockIdx.y * 128;
    for (int k = threadIdx.x; k < B * 128; k += 128) {
        int b = k / 128, dl = k % 128;
        xs[b][dl] = x[b * D + d0 + dl];
    }
    __syncthreads();
    float acc[B];
#pragma unroll
    for (int b = 0; b < B; b++) acc[b] = 0.f;
    for (int dl = 0; dl < 128; dl++) {
        float w = Wenc[(size_t)(d0 + dl) * N0 + i];
#pragma unroll
        for (int b = 0; b < B; b++) acc[b] = fmaf(xs[b][dl], w, acc[b]);
    }
#pragma unroll
    for (int b = 0; b < B; b++) atomicAdd(&g_racc[b * N0 + i], acc[b]);
}

// ---------------- precompute s0/p0 for all T (coalesced over i) ----------------
__global__ void k_pre(const float* __restrict__ u, const float* __restrict__ benc) {
    int idx = blockIdx.x * blockDim.x + threadIdx.x; // over N0*B, i fast
    int i = idx & (N0 - 1), b = idx >> 12;
    float rate = 1.f / (1.f + expf(-(g_racc[b * N0 + i] + benc[i])));
    float V = 0.f, p = 0.f;
    int refr = 0;
    const float* up = u + (size_t)b * T * N0 + i;
    for (int t = 0; t < T; t++) {
        float s_in = (up[(size_t)t * N0] < rate) ? 1.f : 0.f;
        V = DECAY * V + s_in;
        bool spk = (V > THRESH) && (refr <= 0);
        float s = spk ? 1.f : 0.f;
        V = spk ? 0.f : V;
        refr = spk ? 2 : (refr > 0 ? refr - 1 : 0);
        p = TRD * p + s;
        size_t o = (size_t)(t + 1) * N0 * B + (size_t)i * B + b;
        g_s0f[o] = s;
        g_p0f[o] = p;
    }
}

// ---------------- Wa pass: fused STDP update (step t-1) + GEMM cur1(t) ----------------
#define TIA 128
__global__ __launch_bounds__(128, 5) void k_wa(int t) {
    __shared__ float4 sh[TIA * 12]; // [0,TIA*4): p0 | [TIA*4,TIA*8): s0prev | [TIA*8,TIA*12): s0cur
    int j = blockIdx.x * 128 + threadIdx.x;
    int i0 = blockIdx.y * TIA;
    const float* s1prev = g_s1f[(t & 1) ^ 1];

    u64 s1p[8], q0[8], acc[8];
    {
        F4U v;
        const float4* sp = (const float4*)(s1prev + (size_t)j * B);
        const float4* qp = (const float4*)(g_q0n + (size_t)j * B);
#pragma unroll
        for (int q = 0; q < 4; q++) {
            v.f4 = sp[q]; s1p[2 * q] = v.u[0]; s1p[2 * q + 1] = v.u[1];
        }
#pragma unroll
        for (int q = 0; q < 4; q++) {
            v.f4 = qp[q]; q0[2 * q] = v.u[0]; q0[2 * q + 1] = v.u[1];
        }
#pragma unroll
        for (int g = 0; g < 8; g++) acc[g] = 0ull;
    }
    {
        size_t basep = (size_t)t * N0 * B + (size_t)i0 * B;
        const float4* a0 = (const float4*)(g_p0f + basep);
        const float4* a1 = (const float4*)(g_s0f + basep);
        const float4* a2 = (const float4*)(g_s0f + basep + (size_t)N0 * B);
#pragma unroll
        for (int k = threadIdx.x; k < TIA * 4; k += 128) {
            sh[k] = a0[k]; sh[TIA * 4 + k] = a1[k]; sh[TIA * 8 + k] = a2[k];
        }
    }
    __syncthreads();

    const float4* p4 = sh;
    const float4* s4 = sh + TIA * 4;
    const float4* c4 = sh + TIA * 8;
    float* wp = g_Wa + (size_t)i0 * N1 + j;
#pragma unroll 4
    for (int r = 0; r < TIA; r++) {
        float w = wp[(size_t)r * N1];
        u64 d0 = 0ull, d1 = 0ull, d2 = 0ull, d3 = 0ull;
        F4U a, b;
        a.f4 = p4[r * 4 + 0]; b.f4 = p4[r * 4 + 1];
        fma2(d0, a.u[0], s1p[0]); fma2(d1, a.u[1], s1p[1]);
        fma2(d2, b.u[0], s1p[2]); fma2(d3, b.u[1], s1p[3]);
        a.f4 = p4[r * 4 + 2]; b.f4 = p4[r * 4 + 3];
        fma2(d0, a.u[0], s1p[4]); fma2(d1, a.u[1], s1p[5]);
        fma2(d2, b.u[0], s1p[6]); fma2(d3, b.u[1], s1p[7]);
        a.f4 = s4[r * 4 + 0]; b.f4 = s4[r * 4 + 1];
        fma2(d0, a.u[0], q0[0]); fma2(d1, a.u[1], q0[1]);
        fma2(d2, b.u[0], q0[2]); fma2(d3, b.u[1], q0[3]);
        a.f4 = s4[r * 4 + 2]; b.f4 = s4[r * 4 + 3];
        fma2(d0, a.u[0], q0[4]); fma2(d1, a.u[1], q0[5]);
        fma2(d2, b.u[0], q0[6]); fma2(d3, b.u[1], q0[7]);
        u64 e = add2(add2(d0, d1), add2(d2, d3));
        float lo, hi; unpack2(e, lo, hi);
        float nw = fmaf(LR, lo + hi, w);
        nw = fminf(1.f, fmaxf(-1.f, nw));
        wp[(size_t)r * N1] = nw;
        u64 nw2 = pack2(nw, nw);
        a.f4 = c4[r * 4 + 0]; b.f4 = c4[r * 4 + 1];
        fma2(acc[0], a.u[0], nw2); fma2(acc[1], a.u[1], nw2);
        fma2(acc[2], b.u[0], nw2); fma2(acc[3], b.u[1], nw2);
        a.f4 = c4[r * 4 + 2]; b.f4 = c4[r * 4 + 3];
        fma2(acc[4], a.u[0], nw2); fma2(acc[5], a.u[1], nw2);
        fma2(acc[6], b.u[0], nw2); fma2(acc[7], b.u[1], nw2);
    }
#pragma unroll
    for (int g = 0; g < 8; g++) {
        float lo, hi; unpack2(acc[g], lo, hi);
        atomicAdd(&g_cur1[(2 * g) * N1 + j], lo);
        atomicAdd(&g_cur1[(2 * g + 1) * N1 + j], hi);
    }
}

// ---------------- Wb pass: fused STDP update (step t-1) + GEMM cur2(t) ----------------
#define TIB 64
__global__ __launch_bounds__(128, 5) void k_wb(int t) {
    __shared__ float4 sh[TIB * 12]; // p1 | s1prev | s1cur
    int j = blockIdx.x * 128 + threadIdx.x;
    int i0 = blockIdx.y * TIB;
    const float* s1prev = g_s1f[(t & 1) ^ 1];
    const float* s1cur  = g_s1f[t & 1];

    u64 s2p[8], q1[8], acc[8];
    {
        F4U v;
        const float4* sp = (const float4*)(g_s2f + (size_t)j * B);
        const float4* qp = (const float4*)(g_q1n + (size_t)j * B);
#pragma unroll
        for (int q = 0; q < 4; q++) {
            v.f4 = sp[q]; s2p[2 * q] = v.u[0]; s2p[2 * q + 1] = v.u[1];
        }
#pragma unroll
        for (int q = 0; q < 4; q++) {
            v.f4 = qp[q]; q1[2 * q] = v.u[0]; q1[2 * q + 1] = v.u[1];
        }
#pragma unroll
        for (int g = 0; g < 8; g++) acc[g] = 0ull;
    }
    {
        const float4* a0 = (const float4*)(g_p1 + (size_t)i0 * B);
        const float4* a1 = (const float4*)(s1prev + (size_t)i0 * B);
        const float4* a2 = (const float4*)(s1cur + (size_t)i0 * B);
#pragma unroll
        for (int k = threadIdx.x; k < TIB * 4; k += 128) {
            sh[k] = a0[k]; sh[TIB * 4 + k] = a1[k]; sh[TIB * 8 + k] = a2[k];
        }
    }
    __syncthreads();

    const float4* p4 = sh;
    const float4* s4 = sh + TIB * 4;
    const float4* c4 = sh + TIB * 8;
    float* wp = g_Wb + (size_t)i0 * N2 + j;
#pragma unroll 4
    for (int r = 0; r < TIB; r++) {
        float w = wp[(size_t)r * N2];
        u64 d0 = 0ull, d1 = 0ull, d2 = 0ull, d3 = 0ull;
        F4U a, b;
        a.f4 = p4[r * 4 + 0]; b.f4 = p4[r * 4 + 1];
        fma2(d0, a.u[0], s2p[0]); fma2(d1, a.u[1], s2p[1]);
        fma2(d2, b.u[0], s2p[2]); fma2(d3, b.u[1], s2p[3]);
        a.f4 = p4[r * 4 + 2]; b.f4 = p4[r * 4 + 3];
        fma2(d0, a.u[0], s2p[4]); fma2(d1, a.u[1], s2p[5]);
        fma2(d2, b.u[0], s2p[6]); fma2(d3, b.u[1], s2p[7]);
        a.f4 = s4[r * 4 + 0]; b.f4 = s4[r * 4 + 1];
        fma2(d0, a.u[0], q1[0]); fma2(d1, a.u[1], q1[1]);
        fma2(d2, b.u[0], q1[2]); fma2(d3, b.u[1], q1[3]);
        a.f4 = s4[r * 4 + 2]; b.f4 = s4[r * 4 + 3];
        fma2(d0, a.u[0], q1[4]); fma2(d1, a.u[1], q1[5]);
        fma2(d2, b.u[0], q1[6]); fma2(d3, b.u[1], q1[7]);
        u64 e = add2(add2(d0, d1), add2(d2, d3));
        float lo, hi; unpack2(e, lo, hi);
        float nw = fmaf(LR, lo + hi, w);
        nw = fminf(1.f, fmaxf(-1.f, nw));
        wp[(size_t)r * N2] = nw;
        u64 nw2 = pack2(nw, nw);
        a.f4 = c4[r * 4 + 0]; b.f4 = c4[r * 4 + 1];
        fma2(acc[0], a.u[0], nw2); fma2(acc[1], a.u[1], nw2);
        fma2(acc[2], b.u[0], nw2); fma2(acc[3], b.u[1], nw2);
        a.f4 = c4[r * 4 + 2]; b.f4 = c4[r * 4 + 3];
        fma2(acc[4], a.u[0], nw2); fma2(acc[5], a.u[1], nw2);
        fma2(acc[6], b.u[0], nw2); fma2(acc[7], b.u[1], nw2);
    }
#pragma unroll
    for (int g = 0; g < 8; g++) {
        float lo, hi; unpack2(acc[g], lo, hi);
        atomicAdd(&g_cur2[(2 * g) * N2 + j], lo);
        atomicAdd(&g_cur2[(2 * g + 1) * N2 + j], hi);
    }
}

// ---------------- fused LIF: lif1(t) + lif2(t-1) ----------------
__global__ void k_lif12(int t) {
    int idx = blockIdx.x * blockDim.x + threadIdx.x; // over B*N1
    int b = idx / N1, j = idx % N1;
    // --- lif1(t): consume cur1, produce s1(t), update q0n ---
    float cur = g_cur1[idx];
    g_cur1[idx] = 0.f;
    float V = DECAY * g_V1[idx] + cur;
    int refr = g_r1[idx];
    bool spk = (V > THRESH) && (refr <= 0);
    float s = spk ? 1.f : 0.f;
    g_V1[idx] = spk ? 0.f : V;
    g_r1[idx] = spk ? 2 : (refr > 0 ? refr - 1 : 0);
    g_s1f[t & 1][j * B + b] = s;
    float q = g_q0n[j * B + b];
    g_q0n[j * B + b] = TRD * q - s;
    // --- lif2(t-1): consume cur2, produce s2(t-1), update p1/q1n/cnt ---
    if (t > 0) {
        float s1m = g_s1f[(t & 1) ^ 1][j * B + b];
        g_p1[j * B + b] = TRD * g_p1[j * B + b] + s1m;
        if (j < N2) {
            int id2 = b * N2 + j;
            float c2 = g_cur2[id2];
            g_cur2[id2] = 0.f;
            float V2 = DECAY * g_V2[id2] + c2;
            int r2 = g_r2[id2];
            bool sp2 = (V2 > THRESH) && (r2 <= 0);
            float s2 = sp2 ? 1.f : 0.f;
            g_V2[id2] = sp2 ? 0.f : V2;
            g_r2[id2] = sp2 ? 2 : (r2 > 0 ? r2 - 1 : 0);
            g_cnt[id2] += s2;
            g_s2f[j * B + b] = s2;
            float q2 = g_q1n[j * B + b];
            g_q1n[j * B + b] = TRD * q2 - s2;
        }
    }
}

// ---------------- final lif2 (step T-1); p1/q1n/s2f no longer needed, only cnt ----------------
__global__ void k_lif2fin() {
    int idx = blockIdx.x * blockDim.x + threadIdx.x; // over B*N2
    int b = idx / N2, j = idx % N2;
    float c2 = g_cur2[idx];
    float V2 = DECAY * g_V2[idx] + c2;
    int r2 = g_r2[idx];
    bool sp2 = (V2 > THRESH) && (r2 <= 0);
    g_cnt[b * N2 + j] += sp2 ? 1.f : 0.f;
}

// ---------------- readout: out = counts @ W_dec + b_dec ----------------
__global__ void k_out(const float* __restrict__ Wdec, const float* __restrict__ bdec,
                      float* __restrict__ out) {
    int b = blockIdx.x;
    int tid = threadIdx.x;
    int lane = tid & 31, wid = tid >> 5;
    float a[NCLS];
#pragma unroll
    for (int c = 0; c < NCLS; c++) a[c] = 0.f;
    for (int k = tid; k < N2; k += 256) {
        float cv = g_cnt[b * N2 + k];
#pragma unroll
        for (int c = 0; c < NCLS; c++) a[c] = fmaf(cv, Wdec[k * NCLS + c], a[c]);
    }
#pragma unroll
    for (int c = 0; c < NCLS; c++)
#pragma unroll
        for (int o = 16; o > 0; o >>= 1)
            a[c] += __shfl_xor_sync(0xffffffffu, a[c], o);
    __shared__ float sred[8][NCLS];
    if (lane == 0)
#pragma unroll
        for (int c = 0; c < NCLS; c++) sred[wid][c] = a[c];
    __syncthreads();
    if (tid < NCLS) {
        float s = bdec[tid];
#pragma unroll
        for (int w = 0; w < 8; w++) s += sred[w][tid];
        out[b * NCLS + tid] = s;
    }
}

// ---------------- launch ----------------
extern "C" void kernel_launch(void* const* d_in, const int* in_sizes, int n_in,
                              void* d_out, int out_size) {
    (void)in_sizes; (void)n_in; (void)out_size;
    const float* x    = (const float*)d_in[0];
    const float* u    = (const float*)d_in[1];
    const float* Wenc = (const float*)d_in[2];
    const float* benc = (const float*)d_in[3];
    const float* W0   = (const float*)d_in[4];
    const float* W1   = (const float*)d_in[5];
    const float* Wdec = (const float*)d_in[6];
    const float* bdec = (const float*)d_in[7];
    float* out = (float*)d_out;

    cudaMemcpyToSymbolAsync(g_Wa, W0, sizeof(float) * (size_t)N0 * N1, 0,
                            cudaMemcpyDeviceToDevice, 0);
    cudaMemcpyToSymbolAsync(g_Wb, W1, sizeof(float) * (size_t)N1 * N2, 0,
                            cudaMemcpyDeviceToDevice, 0);
    k_init<<<256, 256>>>();
    k_enc<<<dim3(N0 / 128, D / 128), 128>>>(x, Wenc);
    k_pre<<<(N0 * B) / 256, 256>>>(u, benc);
    for (int t = 0; t < T; t++) {
        k_wa<<<dim3(N1 / 128, N0 / TIA), 128>>>(t);
        k_lif12<<<(B * N1) / 256, 256>>>(t);
        k_wb<<<dim3(N2 / 128, N1 / TIB), 128>>>(t);
    }
    k_lif2fin<<<(B * N2) / 256, 256>>>();
    k_out<<<B, 256>>>(Wdec, bdec, out);
}